// round 1
// baseline (speedup 1.0000x reference)
#include <cuda_runtime.h>
#include <cstdint>

// Problem constants
#define Bsz 16
#define Jn  16
#define Cn  64
#define Hn  256
#define Wn  256
#define HW  (Hn * Wn)          // 65536
#define HW4 (HW / 4)           // 16384 float4s

// Scratch for argmax indices (no device allocation allowed)
__device__ int g_argmax[Bsz * Jn];

// ---------------------------------------------------------------------------
// Kernel A: per-(b,j) argmax over heatmap[b,j,:,:] (first-max-index semantics)
// One CTA per (b,j); 256 threads; float4 vectorized grid-stride.
// ---------------------------------------------------------------------------
__global__ __launch_bounds__(256, 8)
void argmax_kernel(const float* __restrict__ heatmap)
{
    const int bj  = blockIdx.x;            // 0..255
    const int tid = threadIdx.x;

    const float4* hm = reinterpret_cast<const float4*>(heatmap + (size_t)bj * HW);

    float best_v = -__FLT_MAX__;
    int   best_i = 0;

    // 64 independent float4 loads per thread -> deep MLP, bandwidth-bound
    #pragma unroll 4
    for (int i = tid; i < HW4; i += 256) {
        float4 v = hm[i];
        int base = i * 4;
        // in-order compare preserves first-occurrence tie-break
        if (v.x > best_v) { best_v = v.x; best_i = base;     }
        else if (v.x == best_v && base     < best_i) best_i = base;
        if (v.y > best_v) { best_v = v.y; best_i = base + 1; }
        else if (v.y == best_v && base + 1 < best_i) best_i = base + 1;
        if (v.z > best_v) { best_v = v.z; best_i = base + 2; }
        else if (v.z == best_v && base + 2 < best_i) best_i = base + 2;
        if (v.w > best_v) { best_v = v.w; best_i = base + 3; }
        else if (v.w == best_v && base + 3 < best_i) best_i = base + 3;
    }

    __shared__ float sv[256];
    __shared__ int   si[256];
    sv[tid] = best_v;
    si[tid] = best_i;
    __syncthreads();

    // tree reduce; keep larger value, lower index on ties
    for (int s = 128; s > 0; s >>= 1) {
        if (tid < s) {
            float ov = sv[tid + s];
            int   oi = si[tid + s];
            if (ov > sv[tid] || (ov == sv[tid] && oi < si[tid])) {
                sv[tid] = ov;
                si[tid] = oi;
            }
        }
        __syncthreads();
    }

    if (tid == 0) g_argmax[bj] = si[0];
}

// ---------------------------------------------------------------------------
// Kernel B: gather pred at argmax, per-(b,j) MSE over C, mean over J.
// One CTA per b; 16 warps; warp w -> joint w; lanes cover C=64 (2 ch/lane).
// ---------------------------------------------------------------------------
__global__ __launch_bounds__(512, 1)
void gather_mse_kernel(const float* __restrict__ pred,
                       const float* __restrict__ gt,
                       float* __restrict__ out)
{
    const int b    = blockIdx.x;
    const int tid  = threadIdx.x;
    const int warp = tid >> 5;     // joint
    const int lane = tid & 31;

    const int idx = g_argmax[b * Jn + warp];

    const float* predb = pred + (size_t)b * Cn * HW;
    const float* gtbj  = gt + ((size_t)b * Jn + warp) * Cn;

    float acc = 0.f;
    #pragma unroll
    for (int k = 0; k < 2; ++k) {
        int c = lane + 32 * k;
        float p = predb[(size_t)c * HW + idx];
        float d = p - gtbj[c];
        acc += d * d;
    }

    // warp reduce
    #pragma unroll
    for (int off = 16; off > 0; off >>= 1)
        acc += __shfl_xor_sync(0xFFFFFFFFu, acc, off);

    __shared__ float sj[Jn];
    if (lane == 0) sj[warp] = acc;
    __syncthreads();

    if (tid == 0) {
        float total = 0.f;
        #pragma unroll
        for (int j = 0; j < Jn; ++j) total += sj[j];
        out[b] = total / (float)(Jn * Cn);
    }
}

// ---------------------------------------------------------------------------
extern "C" void kernel_launch(void* const* d_in, const int* in_sizes, int n_in,
                              void* d_out, int out_size)
{
    const float* pred    = (const float*)d_in[0];  // [B,C,H,W]
    const float* gt      = (const float*)d_in[1];  // [B,J,C]
    const float* heatmap = (const float*)d_in[2];  // [B,J,H,W]
    float* out = (float*)d_out;                    // [B]

    argmax_kernel<<<Bsz * Jn, 256>>>(heatmap);
    gather_mse_kernel<<<Bsz, 512>>>(pred, gt, out);
}